// round 6
// baseline (speedup 1.0000x reference)
#include <cuda_runtime.h>
#include <math.h>

// Problem constants
#define N_A   512
#define N_X   512
#define T_X   1024
#define M_B   64
#define NCOLS 65536          // M_B * T_X
#define A_ELEMS 33554432     // 512*64*1024

// ---------------------------------------------------------------------------
// Persistent-kernel state (small; endorsed scratch mechanism)
// ---------------------------------------------------------------------------
__device__ __align__(16) float g_abuf[2][N_A * M_B];  // ping-pong a_t (compact 512x64)
__device__ unsigned g_bar_cnt = 0;
__device__ unsigned g_bar_gen = 0;

#define REC_BLOCKS 128

__device__ __forceinline__ void grid_barrier() {
    __syncthreads();
    if (threadIdx.x == 0) {
        __threadfence();
        unsigned my = *((volatile unsigned*)&g_bar_gen);
        unsigned prev = atomicAdd(&g_bar_cnt, 1u);
        if (prev == REC_BLOCKS - 1) {
            atomicExch(&g_bar_cnt, 0u);
            __threadfence();
            atomicAdd(&g_bar_gen, 1u);
        } else {
            while (*((volatile unsigned*)&g_bar_gen) == my) { __nanosleep(64); }
        }
        __threadfence();
    }
    __syncthreads();
}

// ---------------------------------------------------------------------------
// SGEMM: C[512, N] = A[512,512] @ B[512, N] + bias[512]
// 128x128 CTA tile, BK=8, 256 threads, 8x8 per thread.
// ---------------------------------------------------------------------------
__global__ void __launch_bounds__(256) sgemm512_bias(
    const float* __restrict__ A, const float* __restrict__ B,
    float* __restrict__ C, const float* __restrict__ bias, int N)
{
    const int K = 512;
    __shared__ float As[8][128];
    __shared__ float Bs[8][128];

    int tid = threadIdx.x;
    int mBlock = blockIdx.y * 128;
    int nBlock = blockIdx.x * 128;

    // A tile load mapping: each thread one float4. row=tid/2, k-offset=(tid&1)*4
    int a_row = tid >> 1;
    int a_k4  = (tid & 1) << 2;
    // B tile load mapping: k=tid/32, col4=(tid%32)*4
    int b_k   = tid >> 5;
    int b_col = (tid & 31) << 2;

    int tr = tid >> 4;            // 0..15
    int tc = tid & 15;            // 0..15
    int m0 = tr * 8, n0 = tc * 8;

    float acc[8][8];
    #pragma unroll
    for (int r = 0; r < 8; ++r)
        #pragma unroll
        for (int c = 0; c < 8; ++c) acc[r][c] = 0.0f;

    const float* Aptr = A + (size_t)(mBlock + a_row) * K + a_k4;
    const float* Bptr = B + (size_t)b_k * N + nBlock + b_col;

    for (int k0 = 0; k0 < K; k0 += 8) {
        float4 av = *(const float4*)(Aptr + k0);
        float4 bv = *(const float4*)(Bptr + (size_t)k0 * N);
        __syncthreads();
        As[a_k4 + 0][a_row] = av.x;
        As[a_k4 + 1][a_row] = av.y;
        As[a_k4 + 2][a_row] = av.z;
        As[a_k4 + 3][a_row] = av.w;
        *(float4*)&Bs[b_k][b_col] = bv;
        __syncthreads();

        #pragma unroll
        for (int kk = 0; kk < 8; ++kk) {
            float4 a0v = *(const float4*)&As[kk][m0];
            float4 a1v = *(const float4*)&As[kk][m0 + 4];
            float4 b0v = *(const float4*)&Bs[kk][n0];
            float4 b1v = *(const float4*)&Bs[kk][n0 + 4];
            float am[8] = {a0v.x, a0v.y, a0v.z, a0v.w, a1v.x, a1v.y, a1v.z, a1v.w};
            float bn[8] = {b0v.x, b0v.y, b0v.z, b0v.w, b1v.x, b1v.y, b1v.z, b1v.w};
            #pragma unroll
            for (int r = 0; r < 8; ++r)
                #pragma unroll
                for (int c = 0; c < 8; ++c)
                    acc[r][c] += am[r] * bn[c];
        }
    }

    #pragma unroll
    for (int r = 0; r < 8; ++r) {
        int row = mBlock + m0 + r;
        float bvl = bias[row];
        float* cp = C + (size_t)row * N + nBlock + n0;
        float4 o0 = make_float4(acc[r][0] + bvl, acc[r][1] + bvl,
                                acc[r][2] + bvl, acc[r][3] + bvl);
        float4 o1 = make_float4(acc[r][4] + bvl, acc[r][5] + bvl,
                                acc[r][6] + bvl, acc[r][7] + bvl);
        *(float4*)cp = o0;
        *(float4*)(cp + 4) = o1;
    }
}

// ---------------------------------------------------------------------------
// Recurrence: persistent kernel. 128 CTAs x 256 threads.
// CTA b owns rows [4b, 4b+4) of Waa (in SMEM, laid out [k][4 rows] as float4).
// Per step: a_next[r,j] = tanh( sum_k Waa[r,k]*a_prev[k,j] + Z[r,j,t] ).
// Thread (s=tid>>4, jq=tid&15): k-slice s (32 k's), columns 4*jq..4*jq+3.
// ---------------------------------------------------------------------------
__global__ void __launch_bounds__(256) rnn_recurrence(
    const float* __restrict__ Waa, const float* __restrict__ a0,
    const float* __restrict__ Z, float* __restrict__ out_a)
{
    __shared__ float4 sW4[512];            // [k] -> 4 rows of this CTA
    __shared__ float  red[16 * 4 * 64];    // [s][r][col]

    int tid = threadIdx.x;
    int r0 = blockIdx.x * 4;

    for (int idx = tid; idx < 2048; idx += 256) {
        int k = idx >> 2, r = idx & 3;
        ((float*)sW4)[idx] = Waa[(size_t)(r0 + r) * 512 + k];
    }
    __syncthreads();

    int jq = tid & 15;        // column quad (4 floats)
    int s  = tid >> 4;        // k-slice 0..15
    int out_r = tid >> 6;     // 0..3
    int out_j = tid & 63;     // 0..63
    int gi = r0 + out_r;

    for (int t = 0; t < T_X; ++t) {
        const float* ap = (t == 0) ? a0 : g_abuf[(t - 1) & 1];
        const float4* ap4 = (const float4*)ap;

        float acc[4][4];
        #pragma unroll
        for (int r = 0; r < 4; ++r)
            #pragma unroll
            for (int c = 0; c < 4; ++c) acc[r][c] = 0.0f;

        int kbase = s * 32;
        #pragma unroll 8
        for (int kk = 0; kk < 32; ++kk) {
            int k = kbase + kk;
            float4 av = ap4[k * 16 + jq];   // a_prev[k, 4jq..4jq+3]
            float4 w  = sW4[k];             // Waa[r0..r0+3, k]
            acc[0][0] += w.x * av.x; acc[0][1] += w.x * av.y;
            acc[0][2] += w.x * av.z; acc[0][3] += w.x * av.w;
            acc[1][0] += w.y * av.x; acc[1][1] += w.y * av.y;
            acc[1][2] += w.y * av.z; acc[1][3] += w.y * av.w;
            acc[2][0] += w.z * av.x; acc[2][1] += w.z * av.y;
            acc[2][2] += w.z * av.z; acc[2][3] += w.z * av.w;
            acc[3][0] += w.w * av.x; acc[3][1] += w.w * av.y;
            acc[3][2] += w.w * av.z; acc[3][3] += w.w * av.w;
        }

        #pragma unroll
        for (int r = 0; r < 4; ++r) {
            float4 v = make_float4(acc[r][0], acc[r][1], acc[r][2], acc[r][3]);
            ((float4*)red)[(s * 4 + r) * 16 + jq] = v;
        }
        __syncthreads();

        float sum = 0.0f;
        #pragma unroll
        for (int ss = 0; ss < 16; ++ss)
            sum += red[(ss * 4 + out_r) * 64 + out_j];

        float z = Z[(size_t)gi * NCOLS + out_j * T_X + t];
        float h = tanhf(sum + z);
        g_abuf[t & 1][gi * M_B + out_j] = h;                      // compact, coalesced
        out_a[(size_t)gi * NCOLS + out_j * T_X + t] = h;          // final layout

        if (t != T_X - 1) grid_barrier();
    }
}

// ---------------------------------------------------------------------------
// Softmax over the batch axis m (stride 1024 in memory), 64 elements/group.
// One thread per (i, t) group; warp-coalesced across t.
// ---------------------------------------------------------------------------
__global__ void __launch_bounds__(256) softmax_batch(float* __restrict__ Y)
{
    int g = blockIdx.x * blockDim.x + threadIdx.x;   // 0 .. 512*1024-1
    int i = g >> 10, t = g & 1023;
    float* base = Y + (size_t)i * NCOLS + t;

    float v[64];
    float mx = -INFINITY;
    #pragma unroll
    for (int j = 0; j < 64; ++j) {
        v[j] = base[j * T_X];
        mx = fmaxf(mx, v[j]);
    }
    float sum = 0.0f;
    #pragma unroll
    for (int j = 0; j < 64; ++j) {
        v[j] = __expf(v[j] - mx);
        sum += v[j];
    }
    float inv = 1.0f / sum;
    #pragma unroll
    for (int j = 0; j < 64; ++j)
        base[j * T_X] = v[j] * inv;
}

// ---------------------------------------------------------------------------
// Launch: GEMM1 (Z into y-half of d_out) -> recurrence -> GEMM2 -> softmax
// ---------------------------------------------------------------------------
extern "C" void kernel_launch(void* const* d_in, const int* in_sizes, int n_in,
                              void* d_out, int out_size)
{
    const float* x   = (const float*)d_in[0];   // (512, 64, 1024) = 512 x 65536
    const float* a0  = (const float*)d_in[1];   // (512, 64)
    const float* Waa = (const float*)d_in[2];   // (512, 512)
    const float* Wax = (const float*)d_in[3];   // (512, 512)
    const float* Wya = (const float*)d_in[4];   // (512, 512)
    const float* ba  = (const float*)d_in[5];   // (512,)
    const float* by  = (const float*)d_in[6];   // (512,)

    float* out_a = (float*)d_out;               // first 512*64*1024 floats
    float* out_y = out_a + A_ELEMS;             // second half; also Z scratch

    dim3 gemm_grid(NCOLS / 128, N_A / 128);     // (512, 4)

    // 1) Z = Wax @ X + ba  (written into y-half, same [i, j*1024+t] layout)
    sgemm512_bias<<<gemm_grid, 256>>>(Wax, x, out_y, ba, NCOLS);

    // 2) sequential recurrence -> out_a
    rnn_recurrence<<<REC_BLOCKS, 256>>>(Waa, a0, out_y, out_a);

    // 3) logits = Wya @ A + by  (overwrites Z in y-half)
    sgemm512_bias<<<gemm_grid, 256>>>(Wya, out_a, out_y, by, NCOLS);

    // 4) softmax over batch axis
    softmax_batch<<<(N_X * T_X) / 256, 256>>>(out_y);
}

// round 7
// speedup vs baseline: 1.2404x; 1.2404x over previous
#include <cuda_runtime.h>
#include <math.h>

// Problem constants
#define N_A   512
#define N_X   512
#define T_X   1024
#define M_B   64
#define NCOLS 65536          // M_B * T_X
#define A_ELEMS 33554432     // 512*64*1024
#define CH    8              // timestep chunk staged in SMEM

// ---------------------------------------------------------------------------
// Persistent-kernel state (small; endorsed scratch mechanism)
// ---------------------------------------------------------------------------
__device__ __align__(16) float g_abuf[2][N_A * M_B];  // ping-pong a_t (compact 512x64)
__device__ unsigned g_bar_cnt = 0;
__device__ unsigned g_bar_gen = 0;

#define REC_BLOCKS 128

// Light grid barrier: acquire/release atomics, no membar.gpu, no nanosleep.
__device__ __forceinline__ void grid_barrier() {
    __syncthreads();
    if (threadIdx.x == 0) {
        unsigned my;
        asm volatile("ld.acquire.gpu.u32 %0, [%1];"
                     : "=r"(my) : "l"(&g_bar_gen) : "memory");
        unsigned prev;
        asm volatile("atom.acq_rel.gpu.add.u32 %0, [%1], %2;"
                     : "=r"(prev) : "l"(&g_bar_cnt), "r"(1u) : "memory");
        if (prev == REC_BLOCKS - 1) {
            asm volatile("st.relaxed.gpu.u32 [%0], %1;"
                         :: "l"(&g_bar_cnt), "r"(0u) : "memory");
            asm volatile("red.release.gpu.add.u32 [%0], %1;"
                         :: "l"(&g_bar_gen), "r"(1u) : "memory");
        } else {
            unsigned g;
            do {
                asm volatile("ld.acquire.gpu.u32 %0, [%1];"
                             : "=r"(g) : "l"(&g_bar_gen) : "memory");
            } while (g == my);
        }
    }
    __syncthreads();
}

// ---------------------------------------------------------------------------
// SGEMM: C[512, N] = A[512,512] @ B[512, N] + bias[512]
// 128x128 CTA tile, BK=8, 256 threads, 8x8 per thread, double-buffered SMEM.
// ---------------------------------------------------------------------------
__global__ void __launch_bounds__(256) sgemm512_bias(
    const float* __restrict__ A, const float* __restrict__ B,
    float* __restrict__ C, const float* __restrict__ bias, int N)
{
    const int K = 512;
    __shared__ __align__(16) float As[2][8][128];
    __shared__ __align__(16) float Bs[2][8][128];

    int tid = threadIdx.x;
    int mBlock = blockIdx.y * 128;
    int nBlock = blockIdx.x * 128;

    int a_row = tid >> 1;
    int a_k4  = (tid & 1) << 2;
    int b_k   = tid >> 5;
    int b_col = (tid & 31) << 2;

    int tr = tid >> 4;            // 0..15
    int tc = tid & 15;            // 0..15
    int m0 = tr * 8, n0 = tc * 8;

    float acc[8][8];
    #pragma unroll
    for (int r = 0; r < 8; ++r)
        #pragma unroll
        for (int c = 0; c < 8; ++c) acc[r][c] = 0.0f;

    const float* Aptr = A + (size_t)(mBlock + a_row) * K + a_k4;
    const float* Bptr = B + (size_t)b_k * N + nBlock + b_col;

    // prologue: tile 0 -> buffer 0
    float4 av = *(const float4*)(Aptr);
    float4 bv = *(const float4*)(Bptr);
    As[0][a_k4 + 0][a_row] = av.x;
    As[0][a_k4 + 1][a_row] = av.y;
    As[0][a_k4 + 2][a_row] = av.z;
    As[0][a_k4 + 3][a_row] = av.w;
    *(float4*)&Bs[0][b_k][b_col] = bv;
    __syncthreads();

    for (int it = 0; it < K / 8; ++it) {
        int cur = it & 1;
        if (it < K / 8 - 1) {
            av = *(const float4*)(Aptr + (it + 1) * 8);
            bv = *(const float4*)(Bptr + (size_t)(it + 1) * 8 * N);
        }

        #pragma unroll
        for (int kk = 0; kk < 8; ++kk) {
            float4 a0v = *(const float4*)&As[cur][kk][m0];
            float4 a1v = *(const float4*)&As[cur][kk][m0 + 4];
            float4 b0v = *(const float4*)&Bs[cur][kk][n0];
            float4 b1v = *(const float4*)&Bs[cur][kk][n0 + 4];
            float am[8] = {a0v.x, a0v.y, a0v.z, a0v.w, a1v.x, a1v.y, a1v.z, a1v.w};
            float bn[8] = {b0v.x, b0v.y, b0v.z, b0v.w, b1v.x, b1v.y, b1v.z, b1v.w};
            #pragma unroll
            for (int r = 0; r < 8; ++r)
                #pragma unroll
                for (int c = 0; c < 8; ++c)
                    acc[r][c] += am[r] * bn[c];
        }

        if (it < K / 8 - 1) {
            int nxt = cur ^ 1;
            As[nxt][a_k4 + 0][a_row] = av.x;
            As[nxt][a_k4 + 1][a_row] = av.y;
            As[nxt][a_k4 + 2][a_row] = av.z;
            As[nxt][a_k4 + 3][a_row] = av.w;
            *(float4*)&Bs[nxt][b_k][b_col] = bv;
            __syncthreads();
        }
    }

    #pragma unroll
    for (int r = 0; r < 8; ++r) {
        int row = mBlock + m0 + r;
        float bvl = bias[row];
        float* cp = C + (size_t)row * N + nBlock + n0;
        float4 o0 = make_float4(acc[r][0] + bvl, acc[r][1] + bvl,
                                acc[r][2] + bvl, acc[r][3] + bvl);
        float4 o1 = make_float4(acc[r][4] + bvl, acc[r][5] + bvl,
                                acc[r][6] + bvl, acc[r][7] + bvl);
        *(float4*)cp = o0;
        *(float4*)(cp + 4) = o1;
    }
}

// ---------------------------------------------------------------------------
// Recurrence: persistent kernel. 128 CTAs x 256 threads.
// CTA b owns rows [4b, 4b+4) of Waa (in SMEM, laid out [k][4 rows] as float4).
// Z and the a-output are staged through SMEM in CH-step chunks so that all
// global traffic at chunk boundaries is float4-coalesced; per-step accesses
// are conflict-free shared-memory ops. Only the compact coalesced g_abuf
// store precedes the grid barrier.
// sZ/sA layout: [tt][p] with row stride 257 floats (p = r*64+j == tid).
// ---------------------------------------------------------------------------
__global__ void __launch_bounds__(256) rnn_recurrence(
    const float* __restrict__ Waa, const float* __restrict__ a0,
    const float* __restrict__ Z, float* __restrict__ out_a)
{
    __shared__ __align__(16) float4 sW4[512];          // 8 KB
    __shared__ __align__(16) float  red[16 * 4 * 64];  // 16 KB
    __shared__ float sZ[CH * 257];                     // ~8 KB
    __shared__ float sA[CH * 257];                     // ~8 KB

    int tid = threadIdx.x;
    int r0 = blockIdx.x * 4;

    for (int idx = tid; idx < 2048; idx += 256) {
        int k = idx >> 2, r = idx & 3;
        ((float*)sW4)[idx] = Waa[(size_t)(r0 + r) * 512 + k];
    }
    __syncthreads();

    int jq = tid & 15;        // column quad (4 floats)
    int s  = tid >> 4;        // k-slice 0..15
    int out_r = tid >> 6;     // 0..3
    int out_j = tid & 63;     // 0..63
    // output pair index p == tid  (out_r*64 + out_j)

    for (int c = 0; c < T_X / CH; ++c) {
        int t0 = c * CH;

        // Stage Z chunk: 4r x 64j x CH t  (coalesced float4 over t)
        #pragma unroll
        for (int i = 0; i < CH / 4; ++i) {
            int e = tid + i * 256;
            int p = e >> (CH == 8 ? 1 : 0);   // CH=8: 2 quads per pair
            int q = e & 1;
            int gi2 = r0 + (p >> 6), j2 = p & 63;
            float4 v = *(const float4*)(Z + (size_t)gi2 * NCOLS + j2 * T_X + t0 + q * 4);
            sZ[(q * 4 + 0) * 257 + p] = v.x;
            sZ[(q * 4 + 1) * 257 + p] = v.y;
            sZ[(q * 4 + 2) * 257 + p] = v.z;
            sZ[(q * 4 + 3) * 257 + p] = v.w;
        }
        // (sZ stores are ordered before first use by the reduction __syncthreads)

        for (int tt = 0; tt < CH; ++tt) {
            int t = t0 + tt;
            const float* ap = (t == 0) ? a0 : g_abuf[(t - 1) & 1];
            const float4* ap4 = (const float4*)ap;

            float acc[4][4];
            #pragma unroll
            for (int r = 0; r < 4; ++r)
                #pragma unroll
                for (int cc = 0; cc < 4; ++cc) acc[r][cc] = 0.0f;

            int kbase = s * 32;
            #pragma unroll 8
            for (int kk = 0; kk < 32; ++kk) {
                int k = kbase + kk;
                float4 avv = ap4[k * 16 + jq];  // a_prev[k, 4jq..4jq+3]
                float4 w  = sW4[k];             // Waa[r0..r0+3, k]
                acc[0][0] += w.x * avv.x; acc[0][1] += w.x * avv.y;
                acc[0][2] += w.x * avv.z; acc[0][3] += w.x * avv.w;
                acc[1][0] += w.y * avv.x; acc[1][1] += w.y * avv.y;
                acc[1][2] += w.y * avv.z; acc[1][3] += w.y * avv.w;
                acc[2][0] += w.z * avv.x; acc[2][1] += w.z * avv.y;
                acc[2][2] += w.z * avv.z; acc[2][3] += w.z * avv.w;
                acc[3][0] += w.w * avv.x; acc[3][1] += w.w * avv.y;
                acc[3][2] += w.w * avv.z; acc[3][3] += w.w * avv.w;
            }

            #pragma unroll
            for (int r = 0; r < 4; ++r) {
                float4 v = make_float4(acc[r][0], acc[r][1], acc[r][2], acc[r][3]);
                ((float4*)red)[(s * 4 + r) * 16 + jq] = v;
            }
            __syncthreads();

            float sum = 0.0f;
            #pragma unroll
            for (int ss = 0; ss < 16; ++ss)
                sum += red[(ss * 4 + out_r) * 64 + out_j];

            float h = tanhf(sum + sZ[tt * 257 + tid]);
            g_abuf[t & 1][r0 * 64 + tid] = h;   // compact, coalesced
            sA[tt * 257 + tid] = h;             // staged final-layout output

            if (t != T_X - 1) grid_barrier();   // includes __syncthreads
        }

        if (c == T_X / CH - 1) __syncthreads(); // last chunk has no trailing barrier

        // Flush a chunk: coalesced float4 over t
        #pragma unroll
        for (int i = 0; i < CH / 4; ++i) {
            int e = tid + i * 256;
            int p = e >> 1;
            int q = e & 1;
            int gi2 = r0 + (p >> 6), j2 = p & 63;
            float4 v;
            v.x = sA[(q * 4 + 0) * 257 + p];
            v.y = sA[(q * 4 + 1) * 257 + p];
            v.z = sA[(q * 4 + 2) * 257 + p];
            v.w = sA[(q * 4 + 3) * 257 + p];
            *(float4*)(out_a + (size_t)gi2 * NCOLS + j2 * T_X + t0 + q * 4) = v;
        }
        // sA/sZ reuse next chunk is ordered by the next reduction __syncthreads.
    }
}

// ---------------------------------------------------------------------------
// Softmax over the batch axis m (stride 1024 in memory), 64 elements/group.
// ---------------------------------------------------------------------------
__global__ void __launch_bounds__(256) softmax_batch(float* __restrict__ Y)
{
    int g = blockIdx.x * blockDim.x + threadIdx.x;   // 0 .. 512*1024-1
    int i = g >> 10, t = g & 1023;
    float* base = Y + (size_t)i * NCOLS + t;

    float v[64];
    float mx = -INFINITY;
    #pragma unroll
    for (int j = 0; j < 64; ++j) {
        v[j] = base[j * T_X];
        mx = fmaxf(mx, v[j]);
    }
    float sum = 0.0f;
    #pragma unroll
    for (int j = 0; j < 64; ++j) {
        v[j] = __expf(v[j] - mx);
        sum += v[j];
    }
    float inv = 1.0f / sum;
    #pragma unroll
    for (int j = 0; j < 64; ++j)
        base[j * T_X] = v[j] * inv;
}

// ---------------------------------------------------------------------------
// Launch: GEMM1 (Z into y-half of d_out) -> recurrence -> GEMM2 -> softmax
// ---------------------------------------------------------------------------
extern "C" void kernel_launch(void* const* d_in, const int* in_sizes, int n_in,
                              void* d_out, int out_size)
{
    const float* x   = (const float*)d_in[0];   // (512, 64, 1024) = 512 x 65536
    const float* a0  = (const float*)d_in[1];   // (512, 64)
    const float* Waa = (const float*)d_in[2];   // (512, 512)
    const float* Wax = (const float*)d_in[3];   // (512, 512)
    const float* Wya = (const float*)d_in[4];   // (512, 512)
    const float* ba  = (const float*)d_in[5];   // (512,)
    const float* by  = (const float*)d_in[6];   // (512,)

    float* out_a = (float*)d_out;               // first 512*64*1024 floats
    float* out_y = out_a + A_ELEMS;             // second half; also Z scratch

    dim3 gemm_grid(NCOLS / 128, N_A / 128);     // (512, 4)

    // 1) Z = Wax @ X + ba  (written into y-half, same [i, j*1024+t] layout)
    sgemm512_bias<<<gemm_grid, 256>>>(Wax, x, out_y, ba, NCOLS);

    // 2) sequential recurrence -> out_a
    rnn_recurrence<<<REC_BLOCKS, 256>>>(Waa, a0, out_y, out_a);

    // 3) logits = Wya @ A + by  (overwrites Z in y-half)
    sgemm512_bias<<<gemm_grid, 256>>>(Wya, out_a, out_y, by, NCOLS);

    // 4) softmax over batch axis
    softmax_batch<<<(N_X * T_X) / 256, 256>>>(out_y);
}

// round 9
// speedup vs baseline: 1.9869x; 1.6018x over previous
#include <cuda_runtime.h>
#include <math.h>

// Problem constants
#define N_A   512
#define N_X   512
#define T_X   1024
#define M_B   64
#define NCOLS 65536          // M_B * T_X
#define A_ELEMS 33554432     // 512*64*1024
#define CH    8              // timestep chunk staged in SMEM

// ---------------------------------------------------------------------------
// Persistent-kernel state (small; endorsed scratch mechanism)
// ---------------------------------------------------------------------------
__device__ __align__(16) float g_abuf[2][N_A * M_B];  // ping-pong a_t (compact 512x64)
__device__ unsigned g_bar_cnt = 0;
__device__ unsigned g_bar_gen = 0;

#define REC_BLOCKS 128

// Light grid barrier: acquire/release atomics, no membar.gpu, no nanosleep.
__device__ __forceinline__ void grid_barrier() {
    __syncthreads();
    if (threadIdx.x == 0) {
        unsigned my;
        asm volatile("ld.acquire.gpu.u32 %0, [%1];"
                     : "=r"(my) : "l"(&g_bar_gen) : "memory");
        unsigned prev;
        asm volatile("atom.acq_rel.gpu.add.u32 %0, [%1], %2;"
                     : "=r"(prev) : "l"(&g_bar_cnt), "r"(1u) : "memory");
        if (prev == REC_BLOCKS - 1) {
            asm volatile("st.relaxed.gpu.u32 [%0], %1;"
                         :: "l"(&g_bar_cnt), "r"(0u) : "memory");
            asm volatile("red.release.gpu.add.u32 [%0], %1;"
                         :: "l"(&g_bar_gen), "r"(1u) : "memory");
        } else {
            unsigned g;
            do {
                asm volatile("ld.acquire.gpu.u32 %0, [%1];"
                             : "=r"(g) : "l"(&g_bar_gen) : "memory");
            } while (g == my);
        }
    }
    __syncthreads();
}

// ---------------------------------------------------------------------------
// SGEMM: C[512, N] = A[512,512] @ B[512, N] + bias[512]
// 128x128 CTA tile, BK=8, 256 threads, 8x8 per thread, double-buffered SMEM.
// ---------------------------------------------------------------------------
__global__ void __launch_bounds__(256) sgemm512_bias(
    const float* __restrict__ A, const float* __restrict__ B,
    float* __restrict__ C, const float* __restrict__ bias, int N)
{
    const int K = 512;
    __shared__ __align__(16) float As[2][8][128];
    __shared__ __align__(16) float Bs[2][8][128];

    int tid = threadIdx.x;
    int mBlock = blockIdx.y * 128;
    int nBlock = blockIdx.x * 128;

    int a_row = tid >> 1;
    int a_k4  = (tid & 1) << 2;
    int b_k   = tid >> 5;
    int b_col = (tid & 31) << 2;

    int tr = tid >> 4;            // 0..15
    int tc = tid & 15;            // 0..15
    int m0 = tr * 8, n0 = tc * 8;

    float acc[8][8];
    #pragma unroll
    for (int r = 0; r < 8; ++r)
        #pragma unroll
        for (int c = 0; c < 8; ++c) acc[r][c] = 0.0f;

    const float* Aptr = A + (size_t)(mBlock + a_row) * K + a_k4;
    const float* Bptr = B + (size_t)b_k * N + nBlock + b_col;

    // prologue: tile 0 -> buffer 0
    float4 av = *(const float4*)(Aptr);
    float4 bv = *(const float4*)(Bptr);
    As[0][a_k4 + 0][a_row] = av.x;
    As[0][a_k4 + 1][a_row] = av.y;
    As[0][a_k4 + 2][a_row] = av.z;
    As[0][a_k4 + 3][a_row] = av.w;
    *(float4*)&Bs[0][b_k][b_col] = bv;
    __syncthreads();

    for (int it = 0; it < K / 8; ++it) {
        int cur = it & 1;
        if (it < K / 8 - 1) {
            av = *(const float4*)(Aptr + (it + 1) * 8);
            bv = *(const float4*)(Bptr + (size_t)(it + 1) * 8 * N);
        }

        #pragma unroll
        for (int kk = 0; kk < 8; ++kk) {
            float4 a0v = *(const float4*)&As[cur][kk][m0];
            float4 a1v = *(const float4*)&As[cur][kk][m0 + 4];
            float4 b0v = *(const float4*)&Bs[cur][kk][n0];
            float4 b1v = *(const float4*)&Bs[cur][kk][n0 + 4];
            float am[8] = {a0v.x, a0v.y, a0v.z, a0v.w, a1v.x, a1v.y, a1v.z, a1v.w};
            float bn[8] = {b0v.x, b0v.y, b0v.z, b0v.w, b1v.x, b1v.y, b1v.z, b1v.w};
            #pragma unroll
            for (int r = 0; r < 8; ++r)
                #pragma unroll
                for (int c = 0; c < 8; ++c)
                    acc[r][c] += am[r] * bn[c];
        }

        if (it < K / 8 - 1) {
            int nxt = cur ^ 1;
            As[nxt][a_k4 + 0][a_row] = av.x;
            As[nxt][a_k4 + 1][a_row] = av.y;
            As[nxt][a_k4 + 2][a_row] = av.z;
            As[nxt][a_k4 + 3][a_row] = av.w;
            *(float4*)&Bs[nxt][b_k][b_col] = bv;
            __syncthreads();
        }
    }

    #pragma unroll
    for (int r = 0; r < 8; ++r) {
        int row = mBlock + m0 + r;
        float bvl = bias[row];
        float* cp = C + (size_t)row * N + nBlock + n0;
        float4 o0 = make_float4(acc[r][0] + bvl, acc[r][1] + bvl,
                                acc[r][2] + bvl, acc[r][3] + bvl);
        float4 o1 = make_float4(acc[r][4] + bvl, acc[r][5] + bvl,
                                acc[r][6] + bvl, acc[r][7] + bvl);
        *(float4*)cp = o0;
        *(float4*)(cp + 4) = o1;
    }
}

// ---------------------------------------------------------------------------
// Recurrence: persistent kernel. 128 CTAs x 256 threads, 2D tiled.
// Grid = 32 row-groups x 4 col-groups; CTA tile = 16 rows x 16 cols.
//   rb = blockIdx.x >> 2  -> rows   r0 = rb*16 .. +15
//   cb = blockIdx.x & 3   -> cols   j0 = cb*16 .. +15
// Each CTA reads only a_prev[:, j0..j0+15] (32 KB) per step -> chip L2
// traffic 4.2 MB/step (was 16.8 MB with 1D row tiling).
// Waa block lives in REGISTERS: thread (s, rg, jq) holds wv[32] float4 =
// Waa[r0+rg*4 .. +3][32s .. 32s+31] (loop-invariant across all 1024 steps).
// Per step each thread: 32 x LDG.128 of a_prev + 512 FFMA; partials reduced
// over the 16 k-slices via SMEM.
// Z / a-output staged through SMEM in CH-step chunks (coalesced float4 at
// chunk boundaries).
// ---------------------------------------------------------------------------
__global__ void __launch_bounds__(256, 1) rnn_recurrence(
    const float* __restrict__ Waa, const float* __restrict__ a0,
    const float* __restrict__ Z, float* __restrict__ out_a)
{
    __shared__ __align__(16) float red[16 * 260];   // [s][lr*16+lj], padded
    __shared__ float sZ[CH * 257];                  // [tt][pair], padded
    __shared__ float sA[CH * 257];

    int tid = threadIdx.x;
    int rb = blockIdx.x >> 2;
    int cb = blockIdx.x & 3;
    int r0 = rb * 16;
    int j0 = cb * 16;

    int jq = tid & 3;          // col quad: cols j0 + jq*4 .. +3
    int rg = (tid >> 2) & 3;   // row group: rows r0 + rg*4 .. +3
    int s  = tid >> 4;         // k-slice: k in [32s, 32s+32)

    // Waa block -> registers (one-time; 4-way duplicated across jq, L1-served)
    float4 wv[32];
    {
        const float* w0 = Waa + (size_t)(r0 + rg * 4 + 0) * 512 + s * 32;
        const float* w1 = Waa + (size_t)(r0 + rg * 4 + 1) * 512 + s * 32;
        const float* w2 = Waa + (size_t)(r0 + rg * 4 + 2) * 512 + s * 32;
        const float* w3 = Waa + (size_t)(r0 + rg * 4 + 3) * 512 + s * 32;
        #pragma unroll
        for (int kk = 0; kk < 32; ++kk) {
            wv[kk].x = w0[kk];
            wv[kk].y = w1[kk];
            wv[kk].z = w2[kk];
            wv[kk].w = w3[kk];
        }
    }

    int out_lr = tid >> 4;     // 0..15 local row
    int out_lj = tid & 15;     // 0..15 local col
    int gr = r0 + out_lr;
    int gj = j0 + out_lj;

    int aq = (j0 >> 2) + jq;   // float4 column index into a_prev (64 floats/row)

    for (int c = 0; c < T_X / CH; ++c) {
        int t0 = c * CH;

        // Stage Z chunk: 16 lr x 16 lj x CH t  (two float4 per thread)
        #pragma unroll
        for (int i = 0; i < 2; ++i) {
            int e = tid + i * 256;
            int p = e >> 1;                 // pair 0..255: lr = p>>4, lj = p&15
            int q = e & 1;                  // which half of the 8 timesteps
            int lr2 = p >> 4, lj2 = p & 15;
            float4 v = *(const float4*)(Z + (size_t)(r0 + lr2) * NCOLS
                                          + (j0 + lj2) * T_X + t0 + q * 4);
            sZ[(q * 4 + 0) * 257 + p] = v.x;
            sZ[(q * 4 + 1) * 257 + p] = v.y;
            sZ[(q * 4 + 2) * 257 + p] = v.z;
            sZ[(q * 4 + 3) * 257 + p] = v.w;
        }
        // ordered before first use by step-0's reduction __syncthreads

        for (int tt = 0; tt < CH; ++tt) {
            int t = t0 + tt;
            const float4* ap4 = (const float4*)((t == 0) ? a0 : g_abuf[(t - 1) & 1]);

            float acc[4][4];
            #pragma unroll
            for (int r = 0; r < 4; ++r)
                #pragma unroll
                for (int cc = 0; cc < 4; ++cc) acc[r][cc] = 0.0f;

            #pragma unroll
            for (int kk = 0; kk < 32; ++kk) {
                float4 avv = ap4[(s * 32 + kk) * 16 + aq];  // a_prev[k, 4 cols]
                float4 w = wv[kk];                           // Waa[4 rows, k]
                acc[0][0] += w.x * avv.x; acc[0][1] += w.x * avv.y;
                acc[0][2] += w.x * avv.z; acc[0][3] += w.x * avv.w;
                acc[1][0] += w.y * avv.x; acc[1][1] += w.y * avv.y;
                acc[1][2] += w.y * avv.z; acc[1][3] += w.y * avv.w;
                acc[2][0] += w.z * avv.x; acc[2][1] += w.z * avv.y;
                acc[2][2] += w.z * avv.z; acc[2][3] += w.z * avv.w;
                acc[3][0] += w.w * avv.x; acc[3][1] += w.w * avv.y;
                acc[3][2] += w.w * avv.z; acc[3][3] += w.w * avv.w;
            }

            // partials: red[s][(rg*4+r)*16 + jq*4 .. +3]
            #pragma unroll
            for (int r = 0; r < 4; ++r) {
                float4 v = make_float4(acc[r][0], acc[r][1], acc[r][2], acc[r][3]);
                *(float4*)&red[s * 260 + (rg * 4 + r) * 16 + jq * 4] = v;
            }
            __syncthreads();

            float sum = 0.0f;
            #pragma unroll
            for (int ss = 0; ss < 16; ++ss)
                sum += red[ss * 260 + out_lr * 16 + out_lj];

            float h = tanhf(sum + sZ[tt * 257 + tid]);
            g_abuf[t & 1][gr * 64 + gj] = h;    // compact state (next step's input)
            sA[tt * 257 + tid] = h;             // staged final-layout output

            if (t != T_X - 1) grid_barrier();   // includes leading __syncthreads
        }

        if (c == T_X / CH - 1) __syncthreads(); // last chunk lacks trailing barrier

        // Flush a chunk (coalesced float4 over t)
        #pragma unroll
        for (int i = 0; i < 2; ++i) {
            int e = tid + i * 256;
            int p = e >> 1;
            int q = e & 1;
            int lr2 = p >> 4, lj2 = p & 15;
            float4 v;
            v.x = sA[(q * 4 + 0) * 257 + p];
            v.y = sA[(q * 4 + 1) * 257 + p];
            v.z = sA[(q * 4 + 2) * 257 + p];
            v.w = sA[(q * 4 + 3) * 257 + p];
            *(float4*)(out_a + (size_t)(r0 + lr2) * NCOLS
                             + (j0 + lj2) * T_X + t0 + q * 4) = v;
        }
        // sA/sZ reuse next chunk ordered by next step's reduction __syncthreads
    }
}

// ---------------------------------------------------------------------------
// Softmax over the batch axis m (stride 1024 in memory), 64 elements/group.
// ---------------------------------------------------------------------------
__global__ void __launch_bounds__(256) softmax_batch(float* __restrict__ Y)
{
    int g = blockIdx.x * blockDim.x + threadIdx.x;   // 0 .. 512*1024-1
    int i = g >> 10, t = g & 1023;
    float* base = Y + (size_t)i * NCOLS + t;

    float v[64];
    float mx = -INFINITY;
    #pragma unroll
    for (int j = 0; j < 64; ++j) {
        v[j] = base[j * T_X];
        mx = fmaxf(mx, v[j]);
    }
    float sum = 0.0f;
    #pragma unroll
    for (int j = 0; j < 64; ++j) {
        v[j] = __expf(v[j] - mx);
        sum += v[j];
    }
    float inv = 1.0f / sum;
    #pragma unroll
    for (int j = 0; j < 64; ++j)
        base[j * T_X] = v[j] * inv;
}

// ---------------------------------------------------------------------------
// Launch: GEMM1 (Z into y-half of d_out) -> recurrence -> GEMM2 -> softmax
// ---------------------------------------------------------------------------
extern "C" void kernel_launch(void* const* d_in, const int* in_sizes, int n_in,
                              void* d_out, int out_size)
{
    const float* x   = (const float*)d_in[0];   // (512, 64, 1024) = 512 x 65536
    const float* a0  = (const float*)d_in[1];   // (512, 64)
    const float* Waa = (const float*)d_in[2];   // (512, 512)
    const float* Wax = (const float*)d_in[3];   // (512, 512)
    const float* Wya = (const float*)d_in[4];   // (512, 512)
    const float* ba  = (const float*)d_in[5];   // (512,)
    const float* by  = (const float*)d_in[6];   // (512,)

    float* out_a = (float*)d_out;               // first 512*64*1024 floats
    float* out_y = out_a + A_ELEMS;             // second half; also Z scratch

    dim3 gemm_grid(NCOLS / 128, N_A / 128);     // (512, 4)

    // 1) Z = Wax @ X + ba  (written into y-half, same [i, j*1024+t] layout)
    sgemm512_bias<<<gemm_grid, 256>>>(Wax, x, out_y, ba, NCOLS);

    // 2) sequential recurrence -> out_a
    rnn_recurrence<<<REC_BLOCKS, 256>>>(Waa, a0, out_y, out_a);

    // 3) logits = Wya @ A + by  (overwrites Z in y-half)
    sgemm512_bias<<<gemm_grid, 256>>>(Wya, out_a, out_y, by, NCOLS);

    // 4) softmax over batch axis
    softmax_batch<<<(N_X * T_X) / 256, 256>>>(out_y);
}